// round 9
// baseline (speedup 1.0000x reference)
#include <cuda_runtime.h>
#include <cuda_bf16.h>
#include <math.h>
#include <stdint.h>

#define NN 50000
#define NE 800000
#define ND 64
#define ED 32
#define NH 128
#define OD 32
#define NL 3
#define NG 128
#define ETILE 64
#define NTILES (NE / ETILE)        // 12500
#define NTILES_N ((NN + 63) / 64)  // 782

// ---------------- device scratch ----------------
__device__ float g_h[NN * ND];
__device__ float g_hd[NN * ND];
__device__ float g_denom[NN];
__device__ float g_agg[NN * ND];
__device__ float g_pooled[NG * ND];
__device__ int   g_cnt[NG];

__device__ __forceinline__ uint32_t f2bf2(float lo, float hi) {
    uint32_t r;
    asm("cvt.rn.bf16x2.f32 %0, %1, %2;" : "=r"(r) : "f"(hi), "f"(lo));
    return r;
}

__device__ __forceinline__ void mma_bf16(float* c, uint32_t a0, uint32_t a1,
                                         uint32_t a2, uint32_t a3,
                                         uint32_t b0, uint32_t b1) {
    asm volatile(
        "mma.sync.aligned.m16n8k16.row.col.f32.bf16.bf16.f32 "
        "{%0,%1,%2,%3}, {%4,%5,%6,%7}, {%8,%9}, {%0,%1,%2,%3};"
        : "+f"(c[0]), "+f"(c[1]), "+f"(c[2]), "+f"(c[3])
        : "r"(a0), "r"(a1), "r"(a2), "r"(a3), "r"(b0), "r"(b1));
}

// ---------------- trivial kernels ----------------
__global__ void k_copy_h(const float* __restrict__ x) {
    int i = blockIdx.x * blockDim.x + threadIdx.x;
    if (i < NN * ND) g_h[i] = x[i];
}

// hd = h @ Wd ; also zero g_agg / g_denom for this layer
__global__ void k_dense(const float* __restrict__ Wd) {
    __shared__ float sW[64 * 64];
    __shared__ float sh[4][64];
    int t = threadIdx.x;
    {
        int i = blockIdx.x * blockDim.x + t;
        int stride = gridDim.x * blockDim.x;
        for (int j = i; j < NN * ND; j += stride) g_agg[j] = 0.f;
        for (int j = i; j < NN; j += stride) g_denom[j] = 0.f;
    }
    for (int i = t; i < 64 * 64; i += 256) sW[i] = Wd[i];
    __syncthreads();
    int r = t >> 6, c = t & 63;
    for (int base = blockIdx.x * 4; base < NN; base += gridDim.x * 4) {
        int n = base + r;
        if (n < NN) sh[r][c] = g_h[n * ND + c];
        __syncthreads();
        if (n < NN) {
            float acc = 0.f;
            #pragma unroll
            for (int k = 0; k < 64; k++) acc = fmaf(sh[r][k], sW[k * 64 + c], acc);
            g_hd[n * ND + c] = acc;
        }
        __syncthreads();
    }
}

// ============ edge MLP via bf16 m16n8k16 MMA, fused direct-exp aggregation ============
// smem bytes: sA[64*80B]=5120 @0 | sHid 17408 @5120 (bf16 [64][136] / fp32 ew [64][68]) |
//             sB1 8192 @22528 | sB2 16384 @30720 | sBias 1024 @47104 -> 48128 B
#define E_O_A 0
#define E_O_HID 5120
#define E_O_B1 22528
#define E_O_B2 30720
#define E_O_BIAS 47104
#define EDGE_SMEM_B 48128

__global__ void __launch_bounds__(256) k_edge_mma(
        const float* __restrict__ ea, const int* __restrict__ ei,
        const float* __restrict__ W1, const float* __restrict__ b1,
        const float* __restrict__ W2, const float* __restrict__ b2,
        const float* __restrict__ av) {
    extern __shared__ char smem[];
    uint32_t* sB1u = (uint32_t*)(smem + E_O_B1);
    uint32_t* sB2u = (uint32_t*)(smem + E_O_B2);
    float* sBias = (float*)(smem + E_O_BIAS);
    int tid = threadIdx.x;
    int lane = tid & 31, wid = tid >> 5;
    int g = lane >> 2, tg = lane & 3;

    // pack W1 fragments (2 ks x 16 ntg)
    for (int idx = tid; idx < 2 * 16 * 32; idx += 256) {
        int l = idx & 31, nt = (idx >> 5) & 15, ks = idx >> 9;
        int gg = l >> 2, tt = l & 3;
        int n = nt * 8 + gg, k0 = ks * 16 + 2 * tt;
        uint2 v;
        v.x = f2bf2(W1[k0 * NH + n], W1[(k0 + 1) * NH + n]);
        v.y = f2bf2(W1[(k0 + 8) * NH + n], W1[(k0 + 9) * NH + n]);
        *(uint2*)(sB1u + (size_t)((ks * 16 + nt) * 64 + 2 * l)) = v;
    }
    // pack W2 fragments (8 ks x 8 ntg)
    for (int idx = tid; idx < 8 * 8 * 32; idx += 256) {
        int l = idx & 31, nt = (idx >> 5) & 7, ks = idx >> 8;
        int gg = l >> 2, tt = l & 3;
        int n = nt * 8 + gg, k0 = ks * 16 + 2 * tt;
        uint2 v;
        v.x = f2bf2(W2[k0 * ND + n], W2[(k0 + 1) * ND + n]);
        v.y = f2bf2(W2[(k0 + 8) * ND + n], W2[(k0 + 9) * ND + n]);
        *(uint2*)(sB2u + (size_t)((ks * 8 + nt) * 64 + 2 * l)) = v;
    }
    if (tid < 128) sBias[tid] = b1[tid];
    if (tid < 64)  sBias[128 + tid] = b2[tid];
    if (tid < 64)  sBias[192 + tid] = av[tid];
    __syncthreads();

    const int* src = ei;
    const int* tgt = ei + NE;
    int mt = wid & 3;
    int nh = wid >> 2;

    for (int tile = blockIdx.x; tile < NTILES; tile += gridDim.x) {
        // ---- load A tile: 64 edges x 32 f32 -> bf16 [64][40] (80 B rows) ----
        {
            int e_l = tid >> 2, q = tid & 3;
            const float4* rp = (const float4*)(ea + (size_t)(tile * ETILE + e_l) * ED + q * 8);
            float4 v0 = rp[0], v1 = rp[1];
            uint4 p;
            p.x = f2bf2(v0.x, v0.y); p.y = f2bf2(v0.z, v0.w);
            p.z = f2bf2(v1.x, v1.y); p.w = f2bf2(v1.z, v1.w);
            *(uint4*)(smem + E_O_A + e_l * 80 + q * 16) = p;
        }
        __syncthreads();

        // ---- GEMM1: hid[64x128] = A @ W1 (K=32, 2 ks) ----
        float C1[8][4];
        #pragma unroll
        for (int nt = 0; nt < 8; nt++)
            C1[nt][0] = C1[nt][1] = C1[nt][2] = C1[nt][3] = 0.f;
        #pragma unroll
        for (int ks = 0; ks < 2; ks++) {
            const char* ab = smem + E_O_A + (mt * 16 + g) * 80 + ks * 32 + 4 * tg;
            uint32_t a0 = *(const uint32_t*)(ab);
            uint32_t a1 = *(const uint32_t*)(ab + 8 * 80);
            uint32_t a2 = *(const uint32_t*)(ab + 16);
            uint32_t a3 = *(const uint32_t*)(ab + 8 * 80 + 16);
            #pragma unroll
            for (int nt = 0; nt < 8; nt++) {
                int ntg = nh * 8 + nt;
                uint2 bf = *(const uint2*)(sB1u + (ks * 16 + ntg) * 64 + 2 * lane);
                mma_bf16(C1[nt], a0, a1, a2, a3, bf.x, bf.y);
            }
        }
        // ---- bias + tanh -> sHid bf16 [64][136] (272 B rows) ----
        #pragma unroll
        for (int nt = 0; nt < 8; nt++) {
            int col = (nh * 8 + nt) * 8 + 2 * tg;
            float bb0 = sBias[col], bb1 = sBias[col + 1];
            uint32_t lo = f2bf2(tanhf(C1[nt][0] + bb0), tanhf(C1[nt][1] + bb1));
            uint32_t hi = f2bf2(tanhf(C1[nt][2] + bb0), tanhf(C1[nt][3] + bb1));
            *(uint32_t*)(smem + E_O_HID + (mt * 16 + g) * 272 + col * 2)     = lo;
            *(uint32_t*)(smem + E_O_HID + (mt * 16 + g + 8) * 272 + col * 2) = hi;
        }
        __syncthreads();

        // ---- GEMM2: ew[64x64] = hid @ W2 (K=128, 8 ks) ----
        float C2[4][4];
        #pragma unroll
        for (int nt = 0; nt < 4; nt++)
            C2[nt][0] = C2[nt][1] = C2[nt][2] = C2[nt][3] = 0.f;
        #pragma unroll
        for (int ks = 0; ks < 8; ks++) {
            const char* ab = smem + E_O_HID + (mt * 16 + g) * 272 + ks * 32 + 4 * tg;
            uint32_t a0 = *(const uint32_t*)(ab);
            uint32_t a1 = *(const uint32_t*)(ab + 8 * 272);
            uint32_t a2 = *(const uint32_t*)(ab + 16);
            uint32_t a3 = *(const uint32_t*)(ab + 8 * 272 + 16);
            #pragma unroll
            for (int nt = 0; nt < 4; nt++) {
                int ntg = nh * 4 + nt;
                uint2 bf = *(const uint2*)(sB2u + (ks * 8 + ntg) * 64 + 2 * lane);
                mma_bf16(C2[nt], a0, a1, a2, a3, bf.x, bf.y);
            }
        }
        __syncthreads();

        // ---- + b2 -> ew fp32 [64][68] over sHid region ----
        {
            float* ewp = (float*)(smem + E_O_HID);
            #pragma unroll
            for (int nt = 0; nt < 4; nt++) {
                int col = (nh * 4 + nt) * 8 + 2 * tg;
                float bb0 = sBias[128 + col], bb1 = sBias[128 + col + 1];
                *(float2*)(ewp + (mt * 16 + g) * 68 + col)     = make_float2(C2[nt][0] + bb0, C2[nt][1] + bb1);
                *(float2*)(ewp + (mt * 16 + g + 8) * 68 + col) = make_float2(C2[nt][2] + bb0, C2[nt][3] + bb1);
            }
        }
        __syncthreads();

        // ---- epilogue: 4 threads/edge; direct-exp fused aggregation ----
        {
            int e_l = tid >> 2, cg = tid & 3;
            int e = tile * ETILE + e_l;
            int s_ = src[e], g_ = tgt[e];
            const float4* hd4 = (const float4*)(g_hd + (size_t)s_ * ND + cg * 16);
            const float* ew = (const float*)(smem + E_O_HID) + e_l * 68 + cg * 16;
            const float* avp = sBias + 192 + cg * 16;
            float4 m[4];
            float sc = 0.f;
            #pragma unroll
            for (int i = 0; i < 4; i++) {
                float4 w = *(const float4*)(ew + 4 * i);
                float4 h = hd4[i];
                m[i] = make_float4(h.x * w.x, h.y * w.y, h.z * w.z, h.w * w.w);
                sc = fmaf(m[i].x, avp[4 * i],     sc);
                sc = fmaf(m[i].y, avp[4 * i + 1], sc);
                sc = fmaf(m[i].z, avp[4 * i + 2], sc);
                sc = fmaf(m[i].w, avp[4 * i + 3], sc);
            }
            sc += __shfl_xor_sync(0xffffffffu, sc, 1);
            sc += __shfl_xor_sync(0xffffffffu, sc, 2);
            float ex = expf(sc);   // scores O(0.1): direct exp == max-subtracted softmax
            if (cg == 0) atomicAdd(&g_denom[g_], ex);
            float* aggp = g_agg + (size_t)g_ * ND + cg * 16;
            #pragma unroll
            for (int i = 0; i < 4; i++) {
                float4 v = make_float4(m[i].x * ex, m[i].y * ex, m[i].z * ex, m[i].w * ex);
                atomicAdd((float4*)(aggp + 4 * i), v);
            }
        }
    }
}

// ============ node update MLP via bf16 MMA (64 nodes/tile) ============
// smem bytes: sA[64*144B]=9216 @0 | sHid 17408 @9216 | sB1 16384 @26624 |
//             sB2 16384 @43008 | sBias 1024 @59392 -> 60416 B
#define N_O_A 0
#define N_O_HID 9216
#define N_O_B1 26624
#define N_O_B2 43008
#define N_O_BIAS 59392
#define NODE_SMEM_B 60416

__global__ void __launch_bounds__(256) k_node_mma(
        const float* __restrict__ W1, const float* __restrict__ b1,
        const float* __restrict__ W2, const float* __restrict__ b2,
        const int* __restrict__ batch, int do_pool) {
    extern __shared__ char smem[];
    uint32_t* sB1u = (uint32_t*)(smem + N_O_B1);
    uint32_t* sB2u = (uint32_t*)(smem + N_O_B2);
    float* sBias = (float*)(smem + N_O_BIAS);
    int tid = threadIdx.x;
    int lane = tid & 31, wid = tid >> 5;
    int g = lane >> 2, tg = lane & 3;

    // pack W1 [64x128] fragments (4 ks x 16 ntg)
    for (int idx = tid; idx < 4 * 16 * 32; idx += 256) {
        int l = idx & 31, nt = (idx >> 5) & 15, ks = idx >> 9;
        int gg = l >> 2, tt = l & 3;
        int n = nt * 8 + gg, k0 = ks * 16 + 2 * tt;
        uint2 v;
        v.x = f2bf2(W1[k0 * NH + n], W1[(k0 + 1) * NH + n]);
        v.y = f2bf2(W1[(k0 + 8) * NH + n], W1[(k0 + 9) * NH + n]);
        *(uint2*)(sB1u + (size_t)((ks * 16 + nt) * 64 + 2 * l)) = v;
    }
    // pack W2 [128x64] fragments (8 ks x 8 ntg)
    for (int idx = tid; idx < 8 * 8 * 32; idx += 256) {
        int l = idx & 31, nt = (idx >> 5) & 7, ks = idx >> 8;
        int gg = l >> 2, tt = l & 3;
        int n = nt * 8 + gg, k0 = ks * 16 + 2 * tt;
        uint2 v;
        v.x = f2bf2(W2[k0 * ND + n], W2[(k0 + 1) * ND + n]);
        v.y = f2bf2(W2[(k0 + 8) * ND + n], W2[(k0 + 9) * ND + n]);
        *(uint2*)(sB2u + (size_t)((ks * 8 + nt) * 64 + 2 * l)) = v;
    }
    if (tid < 128) sBias[tid] = b1[tid];
    if (tid < 64)  sBias[128 + tid] = b2[tid];
    __syncthreads();

    int mt = wid & 3;
    int nh = wid >> 2;

    for (int tile = blockIdx.x; tile < NTILES_N; tile += gridDim.x) {
        int base = tile * 64;
        int nrows = NN - base; if (nrows > 64) nrows = 64;
        // ---- load A = agg/denom -> bf16 [64][72] (144 B rows) ----
        {
            int e_l = tid >> 2, q = tid & 3;
            float4 v0 = make_float4(0.f,0.f,0.f,0.f), v1 = v0, v2 = v0, v3 = v0;
            if (e_l < nrows) {
                int n = base + e_l;
                float dn = g_denom[n];
                float invd = dn > 0.f ? 1.f / dn : 0.f;
                const float4* rp = (const float4*)(g_agg + (size_t)n * ND + q * 16);
                v0 = rp[0]; v1 = rp[1]; v2 = rp[2]; v3 = rp[3];
                v0.x *= invd; v0.y *= invd; v0.z *= invd; v0.w *= invd;
                v1.x *= invd; v1.y *= invd; v1.z *= invd; v1.w *= invd;
                v2.x *= invd; v2.y *= invd; v2.z *= invd; v2.w *= invd;
                v3.x *= invd; v3.y *= invd; v3.z *= invd; v3.w *= invd;
            }
            uint4 pA, pB;
            pA.x = f2bf2(v0.x, v0.y); pA.y = f2bf2(v0.z, v0.w);
            pA.z = f2bf2(v1.x, v1.y); pA.w = f2bf2(v1.z, v1.w);
            pB.x = f2bf2(v2.x, v2.y); pB.y = f2bf2(v2.z, v2.w);
            pB.z = f2bf2(v3.x, v3.y); pB.w = f2bf2(v3.z, v3.w);
            *(uint4*)(smem + N_O_A + e_l * 144 + q * 32)      = pA;
            *(uint4*)(smem + N_O_A + e_l * 144 + q * 32 + 16) = pB;
        }
        __syncthreads();

        // ---- GEMM1: hid = A @ W1 (K=64, 4 ks) ----
        float C1[8][4];
        #pragma unroll
        for (int nt = 0; nt < 8; nt++)
            C1[nt][0] = C1[nt][1] = C1[nt][2] = C1[nt][3] = 0.f;
        #pragma unroll
        for (int ks = 0; ks < 4; ks++) {
            const char* ab = smem + N_O_A + (mt * 16 + g) * 144 + ks * 32 + 4 * tg;
            uint32_t a0 = *(const uint32_t*)(ab);
            uint32_t a1 = *(const uint32_t*)(ab + 8 * 144);
            uint32_t a2 = *(const uint32_t*)(ab + 16);
            uint32_t a3 = *(const uint32_t*)(ab + 8 * 144 + 16);
            #pragma unroll
            for (int nt = 0; nt < 8; nt++) {
                int ntg = nh * 8 + nt;
                uint2 bf = *(const uint2*)(sB1u + (ks * 16 + ntg) * 64 + 2 * lane);
                mma_bf16(C1[nt], a0, a1, a2, a3, bf.x, bf.y);
            }
        }
        #pragma unroll
        for (int nt = 0; nt < 8; nt++) {
            int col = (nh * 8 + nt) * 8 + 2 * tg;
            float bb0 = sBias[col], bb1 = sBias[col + 1];
            uint32_t lo = f2bf2(tanhf(C1[nt][0] + bb0), tanhf(C1[nt][1] + bb1));
            uint32_t hi = f2bf2(tanhf(C1[nt][2] + bb0), tanhf(C1[nt][3] + bb1));
            *(uint32_t*)(smem + N_O_HID + (mt * 16 + g) * 272 + col * 2)     = lo;
            *(uint32_t*)(smem + N_O_HID + (mt * 16 + g + 8) * 272 + col * 2) = hi;
        }
        __syncthreads();

        // ---- GEMM2: delta = hid @ W2 (K=128, 8 ks) ----
        float C2[4][4];
        #pragma unroll
        for (int nt = 0; nt < 4; nt++)
            C2[nt][0] = C2[nt][1] = C2[nt][2] = C2[nt][3] = 0.f;
        #pragma unroll
        for (int ks = 0; ks < 8; ks++) {
            const char* ab = smem + N_O_HID + (mt * 16 + g) * 272 + ks * 32 + 4 * tg;
            uint32_t a0 = *(const uint32_t*)(ab);
            uint32_t a1 = *(const uint32_t*)(ab + 8 * 272);
            uint32_t a2 = *(const uint32_t*)(ab + 16);
            uint32_t a3 = *(const uint32_t*)(ab + 8 * 272 + 16);
            #pragma unroll
            for (int nt = 0; nt < 4; nt++) {
                int ntg = nh * 4 + nt;
                uint2 bf = *(const uint2*)(sB2u + (ks * 8 + ntg) * 64 + 2 * lane);
                mma_bf16(C2[nt], a0, a1, a2, a3, bf.x, bf.y);
            }
        }
        __syncthreads();

        {
            float* dwp = (float*)(smem + N_O_HID);
            #pragma unroll
            for (int nt = 0; nt < 4; nt++) {
                int col = (nh * 4 + nt) * 8 + 2 * tg;
                float bb0 = sBias[128 + col], bb1 = sBias[128 + col + 1];
                *(float2*)(dwp + (mt * 16 + g) * 68 + col)     = make_float2(C2[nt][0] + bb0, C2[nt][1] + bb1);
                *(float2*)(dwp + (mt * 16 + g + 8) * 68 + col) = make_float2(C2[nt][2] + bb0, C2[nt][3] + bb1);
            }
        }
        __syncthreads();

        // ---- epilogue: h += delta, optional fused pooling ----
        {
            int e_l = tid >> 2, cg = tid & 3;
            if (e_l < nrows) {
                int n = base + e_l;
                float* hp = g_h + (size_t)n * ND + cg * 16;
                const float* dw = (const float*)(smem + N_O_HID) + e_l * 68 + cg * 16;
                float4 hv[4];
                #pragma unroll
                for (int i = 0; i < 4; i++) {
                    float4 h = *(float4*)(hp + 4 * i);
                    float4 d = *(const float4*)(dw + 4 * i);
                    hv[i] = make_float4(h.x + d.x, h.y + d.y, h.z + d.z, h.w + d.w);
                    *(float4*)(hp + 4 * i) = hv[i];
                }
                if (do_pool) {
                    int b = batch[n];
                    float* pp = g_pooled + b * ND + cg * 16;
                    #pragma unroll
                    for (int i = 0; i < 4; i++)
                        atomicAdd((float4*)(pp + 4 * i), hv[i]);
                    if (cg == 0) atomicAdd(&g_cnt[b], 1);
                }
            }
        }
    }
}

// ---------------- pooling init + final MLP ----------------
__global__ void k_pool_init() {
    int i = threadIdx.x + blockIdx.x * blockDim.x;
    if (i < NG * ND) g_pooled[i] = 0.f;
    if (i < NG) g_cnt[i] = 0;
}

#define FINAL_SMEM_F (8192 + 4096 + 128 + 32 + 512 + 1024)
__global__ void k_final(const float* __restrict__ W1, const float* __restrict__ b1,
                        const float* __restrict__ W2, const float* __restrict__ b2,
                        float* __restrict__ out) {
    extern __shared__ float sm[];
    float* sW1  = sm;
    float* sW2  = sm + 8192;
    float* sb1  = sm + 12288;
    float* sb2  = sm + 12416;
    float* sP   = sm + 12448;
    float* sHid = sm + 12960;
    int t = threadIdx.x;
    for (int i = t; i < 8192; i += 256) sW1[i] = W1[i];
    for (int i = t; i < 4096; i += 256) sW2[i] = W2[i];
    if (t < 128) sb1[t] = b1[t];
    if (t < 32) sb2[t] = b2[t];
    __syncthreads();

    int w = t >> 5, l = t & 31;
    int g = blockIdx.x * 8 + w;
    if (g >= NG) return;
    float inv = 1.f / (float)max(g_cnt[g], 1);
    float* pw   = sP + w * 64;
    float* hidw = sHid + w * 128;
    float2 pv = *(const float2*)(g_pooled + g * ND + 2 * l);
    pw[2 * l] = pv.x * inv;
    pw[2 * l + 1] = pv.y * inv;
    __syncwarp();
    float4 acc = *(const float4*)(sb1 + 4 * l);
    #pragma unroll 8
    for (int k = 0; k < 64; k++) {
        float a = pw[k];
        float4 wv = *(const float4*)(sW1 + k * 128 + 4 * l);
        acc.x = fmaf(a, wv.x, acc.x);
        acc.y = fmaf(a, wv.y, acc.y);
        acc.z = fmaf(a, wv.z, acc.z);
        acc.w = fmaf(a, wv.w, acc.w);
    }
    acc.x = tanhf(acc.x); acc.y = tanhf(acc.y);
    acc.z = tanhf(acc.z); acc.w = tanhf(acc.w);
    *(float4*)(hidw + 4 * l) = acc;
    __syncwarp();
    float o = sb2[l];
    #pragma unroll 8
    for (int k = 0; k < 128; k += 4) {
        float4 hv = *(const float4*)(hidw + k);
        o = fmaf(hv.x, sW2[(k    ) * 32 + l], o);
        o = fmaf(hv.y, sW2[(k + 1) * 32 + l], o);
        o = fmaf(hv.z, sW2[(k + 2) * 32 + l], o);
        o = fmaf(hv.w, sW2[(k + 3) * 32 + l], o);
    }
    out[g * OD + l] = o;
}

// ---------------- launch ----------------
extern "C" void kernel_launch(void* const* d_in, const int* in_sizes, int n_in,
                              void* d_out, int out_size) {
    const float *x, *ea, *Wd, *fW1, *fb1, *fW2, *fb2, *av;
    const float *oW1, *ob1, *oW2, *ob2, *nW1, *nb1, *nW2, *nb2;
    const int *ei, *batch;

    if (in_sizes[2] == 2 * NE) {
        x   = (const float*)d_in[0];  ea  = (const float*)d_in[1];
        ei  = (const int*)  d_in[2];  batch = (const int*)d_in[3];
        Wd  = (const float*)d_in[4];
        fW1 = (const float*)d_in[5];  fb1 = (const float*)d_in[6];
        fW2 = (const float*)d_in[7];  fb2 = (const float*)d_in[8];
        av  = (const float*)d_in[9];
        oW1 = (const float*)d_in[10]; ob1 = (const float*)d_in[11];
        oW2 = (const float*)d_in[12]; ob2 = (const float*)d_in[13];
        nW1 = (const float*)d_in[14]; nb1 = (const float*)d_in[15];
        nW2 = (const float*)d_in[16]; nb2 = (const float*)d_in[17];
    } else {
        x   = (const float*)d_in[0];  ea  = (const float*)d_in[1];
        Wd  = (const float*)d_in[2];
        fW1 = (const float*)d_in[3];  fb1 = (const float*)d_in[4];
        fW2 = (const float*)d_in[5];  fb2 = (const float*)d_in[6];
        av  = (const float*)d_in[7];
        oW1 = (const float*)d_in[8];  ob1 = (const float*)d_in[9];
        oW2 = (const float*)d_in[10]; ob2 = (const float*)d_in[11];
        nW1 = (const float*)d_in[12]; nb1 = (const float*)d_in[13];
        nW2 = (const float*)d_in[14]; nb2 = (const float*)d_in[15];
        ei  = (const int*)d_in[16];   batch = (const int*)d_in[17];
    }

    cudaFuncSetAttribute(k_edge_mma, cudaFuncAttributeMaxDynamicSharedMemorySize,
                         EDGE_SMEM_B);
    cudaFuncSetAttribute(k_node_mma, cudaFuncAttributeMaxDynamicSharedMemorySize,
                         NODE_SMEM_B);
    cudaFuncSetAttribute(k_final, cudaFuncAttributeMaxDynamicSharedMemorySize,
                         FINAL_SMEM_F * 4);

    k_copy_h<<<(NN * ND + 255) / 256, 256>>>(x);
    k_pool_init<<<(NG * ND + 255) / 256, 256>>>();

    for (int i = 0; i < NL; i++) {
        k_dense<<<1480, 256>>>(Wd + i * ND * ND);
        k_edge_mma<<<592, 256, EDGE_SMEM_B>>>(
            ea, ei,
            fW1 + i * ED * NH, fb1 + i * NH,
            fW2 + i * NH * ND, fb2 + i * ND,
            av + i * ND);
        k_node_mma<<<444, 256, NODE_SMEM_B>>>(
            oW1 + i * ND * NH, ob1 + i * NH,
            oW2 + i * NH * ND, ob2 + i * ND,
            batch, (i == NL - 1) ? 1 : 0);
    }

    k_final<<<16, 256, FINAL_SMEM_F * 4>>>(nW1, nb1, nW2, nb2, (float*)d_out);
}

// round 10
// speedup vs baseline: 1.0959x; 1.0959x over previous
#include <cuda_runtime.h>
#include <cuda_bf16.h>
#include <math.h>
#include <stdint.h>

#define NN 50000
#define NE 800000
#define ND 64
#define ED 32
#define NH 128
#define OD 32
#define NL 3
#define NG 128
#define ETILE 64
#define NTILES (NE / ETILE)        // 12500
#define NTILES_N ((NN + 63) / 64)  // 782

// ---------------- device scratch ----------------
__device__ float g_h[NN * ND];
__device__ float g_hd[NN * ND];
__device__ float g_denom[NN];
__device__ float g_agg[NN * ND];
__device__ float g_pooled[NG * ND];
__device__ int   g_cnt[NG];

__device__ __forceinline__ uint32_t f2bf2(float lo, float hi) {
    uint32_t r;
    asm("cvt.rn.bf16x2.f32 %0, %1, %2;" : "=r"(r) : "f"(hi), "f"(lo));
    return r;
}

__device__ __forceinline__ float tanha(float x) {
    float r;
    asm("tanh.approx.f32 %0, %1;" : "=f"(r) : "f"(x));
    return r;
}

__device__ __forceinline__ void mma_bf16(float* c, uint32_t a0, uint32_t a1,
                                         uint32_t a2, uint32_t a3,
                                         uint32_t b0, uint32_t b1) {
    asm volatile(
        "mma.sync.aligned.m16n8k16.row.col.f32.bf16.bf16.f32 "
        "{%0,%1,%2,%3}, {%4,%5,%6,%7}, {%8,%9}, {%0,%1,%2,%3};"
        : "+f"(c[0]), "+f"(c[1]), "+f"(c[2]), "+f"(c[3])
        : "r"(a0), "r"(a1), "r"(a2), "r"(a3), "r"(b0), "r"(b1));
}

// ldmatrix x4: loads the full A fragment (a0..a3) of m16n8k16 in one instruction.
// Caller passes this thread's row pointer: row = lane&15, byte col offset = (lane>>4)*16.
__device__ __forceinline__ void ldmA(uint32_t& a0, uint32_t& a1, uint32_t& a2,
                                     uint32_t& a3, const void* p) {
    uint32_t addr = (uint32_t)__cvta_generic_to_shared(p);
    asm volatile("ldmatrix.sync.aligned.m8n8.x4.shared.b16 {%0,%1,%2,%3}, [%4];"
                 : "=r"(a0), "=r"(a1), "=r"(a2), "=r"(a3) : "r"(addr));
}

// ---------------- trivial kernels ----------------
__global__ void k_copy_h(const float* __restrict__ x) {
    int i = blockIdx.x * blockDim.x + threadIdx.x;
    if (i < NN * ND) g_h[i] = x[i];
}

// hd = h @ Wd ; also zero g_agg / g_denom for this layer
__global__ void k_dense(const float* __restrict__ Wd) {
    __shared__ float sW[64 * 64];
    __shared__ float sh[4][64];
    int t = threadIdx.x;
    {
        int i = blockIdx.x * blockDim.x + t;
        int stride = gridDim.x * blockDim.x;
        for (int j = i; j < NN * ND; j += stride) g_agg[j] = 0.f;
        for (int j = i; j < NN; j += stride) g_denom[j] = 0.f;
    }
    for (int i = t; i < 64 * 64; i += 256) sW[i] = Wd[i];
    __syncthreads();
    int r = t >> 6, c = t & 63;
    for (int base = blockIdx.x * 4; base < NN; base += gridDim.x * 4) {
        int n = base + r;
        if (n < NN) sh[r][c] = g_h[n * ND + c];
        __syncthreads();
        if (n < NN) {
            float acc = 0.f;
            #pragma unroll
            for (int k = 0; k < 64; k++) acc = fmaf(sh[r][k], sW[k * 64 + c], acc);
            g_hd[n * ND + c] = acc;
        }
        __syncthreads();
    }
}

// ============ edge MLP via bf16 m16n8k16 MMA + ldmatrix, fused aggregation ============
#define E_O_A 0
#define E_O_HID 5120
#define E_O_B1 22528
#define E_O_B2 30720
#define E_O_BIAS 47104
#define EDGE_SMEM_B 48128

__global__ void __launch_bounds__(256) k_edge_mma(
        const float* __restrict__ ea, const int* __restrict__ ei,
        const float* __restrict__ W1, const float* __restrict__ b1,
        const float* __restrict__ W2, const float* __restrict__ b2,
        const float* __restrict__ av) {
    extern __shared__ char smem[];
    uint32_t* sB1u = (uint32_t*)(smem + E_O_B1);
    uint32_t* sB2u = (uint32_t*)(smem + E_O_B2);
    float* sBias = (float*)(smem + E_O_BIAS);
    int tid = threadIdx.x;
    int lane = tid & 31, wid = tid >> 5;
    int g = lane >> 2, tg = lane & 3;

    // pack W1 fragments (2 ks x 16 ntg)
    for (int idx = tid; idx < 2 * 16 * 32; idx += 256) {
        int l = idx & 31, nt = (idx >> 5) & 15, ks = idx >> 9;
        int gg = l >> 2, tt = l & 3;
        int n = nt * 8 + gg, k0 = ks * 16 + 2 * tt;
        uint2 v;
        v.x = f2bf2(W1[k0 * NH + n], W1[(k0 + 1) * NH + n]);
        v.y = f2bf2(W1[(k0 + 8) * NH + n], W1[(k0 + 9) * NH + n]);
        *(uint2*)(sB1u + (size_t)((ks * 16 + nt) * 64 + 2 * l)) = v;
    }
    // pack W2 fragments (8 ks x 8 ntg)
    for (int idx = tid; idx < 8 * 8 * 32; idx += 256) {
        int l = idx & 31, nt = (idx >> 5) & 7, ks = idx >> 8;
        int gg = l >> 2, tt = l & 3;
        int n = nt * 8 + gg, k0 = ks * 16 + 2 * tt;
        uint2 v;
        v.x = f2bf2(W2[k0 * ND + n], W2[(k0 + 1) * ND + n]);
        v.y = f2bf2(W2[(k0 + 8) * ND + n], W2[(k0 + 9) * ND + n]);
        *(uint2*)(sB2u + (size_t)((ks * 8 + nt) * 64 + 2 * l)) = v;
    }
    if (tid < 128) sBias[tid] = b1[tid];
    if (tid < 64)  sBias[128 + tid] = b2[tid];
    if (tid < 64)  sBias[192 + tid] = av[tid];
    __syncthreads();

    const int* src = ei;
    const int* tgt = ei + NE;
    int mt = wid & 3;
    int nh = wid >> 2;
    int lrow = lane & 15;           // ldmatrix row within m16 tile
    int lcol = (lane >> 4) * 16;    // ldmatrix 16B column offset

    for (int tile = blockIdx.x; tile < NTILES; tile += gridDim.x) {
        // ---- load A tile: 64 edges x 32 f32 -> bf16 [64][40] (80 B rows) ----
        {
            int e_l = tid >> 2, q = tid & 3;
            const float4* rp = (const float4*)(ea + (size_t)(tile * ETILE + e_l) * ED + q * 8);
            float4 v0 = rp[0], v1 = rp[1];
            uint4 p;
            p.x = f2bf2(v0.x, v0.y); p.y = f2bf2(v0.z, v0.w);
            p.z = f2bf2(v1.x, v1.y); p.w = f2bf2(v1.z, v1.w);
            *(uint4*)(smem + E_O_A + e_l * 80 + q * 16) = p;
        }
        __syncthreads();

        // ---- GEMM1: hid[64x128] = A @ W1 (K=32, 2 ks) ----
        float C1[8][4];
        #pragma unroll
        for (int nt = 0; nt < 8; nt++)
            C1[nt][0] = C1[nt][1] = C1[nt][2] = C1[nt][3] = 0.f;
        #pragma unroll
        for (int ks = 0; ks < 2; ks++) {
            uint32_t a0, a1, a2, a3;
            ldmA(a0, a1, a2, a3,
                 smem + E_O_A + (mt * 16 + lrow) * 80 + ks * 32 + lcol);
            #pragma unroll
            for (int nt = 0; nt < 8; nt++) {
                int ntg = nh * 8 + nt;
                uint2 bf = *(const uint2*)(sB1u + (ks * 16 + ntg) * 64 + 2 * lane);
                mma_bf16(C1[nt], a0, a1, a2, a3, bf.x, bf.y);
            }
        }
        // ---- bias + tanh -> sHid bf16 [64][136] (272 B rows) ----
        #pragma unroll
        for (int nt = 0; nt < 8; nt++) {
            int col = (nh * 8 + nt) * 8 + 2 * tg;
            float bb0 = sBias[col], bb1 = sBias[col + 1];
            uint32_t lo = f2bf2(tanha(C1[nt][0] + bb0), tanha(C1[nt][1] + bb1));
            uint32_t hi = f2bf2(tanha(C1[nt][2] + bb0), tanha(C1[nt][3] + bb1));
            *(uint32_t*)(smem + E_O_HID + (mt * 16 + g) * 272 + col * 2)     = lo;
            *(uint32_t*)(smem + E_O_HID + (mt * 16 + g + 8) * 272 + col * 2) = hi;
        }
        __syncthreads();

        // ---- GEMM2: ew[64x64] = hid @ W2 (K=128, 8 ks) ----
        float C2[4][4];
        #pragma unroll
        for (int nt = 0; nt < 4; nt++)
            C2[nt][0] = C2[nt][1] = C2[nt][2] = C2[nt][3] = 0.f;
        #pragma unroll
        for (int ks = 0; ks < 8; ks++) {
            uint32_t a0, a1, a2, a3;
            ldmA(a0, a1, a2, a3,
                 smem + E_O_HID + (mt * 16 + lrow) * 272 + ks * 32 + lcol);
            #pragma unroll
            for (int nt = 0; nt < 4; nt++) {
                int ntg = nh * 4 + nt;
                uint2 bf = *(const uint2*)(sB2u + (ks * 8 + ntg) * 64 + 2 * lane);
                mma_bf16(C2[nt], a0, a1, a2, a3, bf.x, bf.y);
            }
        }
        __syncthreads();

        // ---- + b2 -> ew fp32 [64][68] over sHid region ----
        {
            float* ewp = (float*)(smem + E_O_HID);
            #pragma unroll
            for (int nt = 0; nt < 4; nt++) {
                int col = (nh * 4 + nt) * 8 + 2 * tg;
                float bb0 = sBias[128 + col], bb1 = sBias[128 + col + 1];
                *(float2*)(ewp + (mt * 16 + g) * 68 + col)     = make_float2(C2[nt][0] + bb0, C2[nt][1] + bb1);
                *(float2*)(ewp + (mt * 16 + g + 8) * 68 + col) = make_float2(C2[nt][2] + bb0, C2[nt][3] + bb1);
            }
        }
        __syncthreads();

        // ---- epilogue: 4 threads/edge; direct-exp fused aggregation ----
        {
            int e_l = tid >> 2, cg = tid & 3;
            int e = tile * ETILE + e_l;
            int s_ = src[e], g_ = tgt[e];
            const float4* hd4 = (const float4*)(g_hd + (size_t)s_ * ND + cg * 16);
            const float* ew = (const float*)(smem + E_O_HID) + e_l * 68 + cg * 16;
            const float* avp = sBias + 192 + cg * 16;
            float4 m[4];
            float sc = 0.f;
            #pragma unroll
            for (int i = 0; i < 4; i++) {
                float4 w = *(const float4*)(ew + 4 * i);
                float4 h = hd4[i];
                m[i] = make_float4(h.x * w.x, h.y * w.y, h.z * w.z, h.w * w.w);
                sc = fmaf(m[i].x, avp[4 * i],     sc);
                sc = fmaf(m[i].y, avp[4 * i + 1], sc);
                sc = fmaf(m[i].z, avp[4 * i + 2], sc);
                sc = fmaf(m[i].w, avp[4 * i + 3], sc);
            }
            sc += __shfl_xor_sync(0xffffffffu, sc, 1);
            sc += __shfl_xor_sync(0xffffffffu, sc, 2);
            float ex = __expf(sc);   // scores O(0.1): direct exp == max-subtracted softmax
            if (cg == 0) atomicAdd(&g_denom[g_], ex);
            float* aggp = g_agg + (size_t)g_ * ND + cg * 16;
            #pragma unroll
            for (int i = 0; i < 4; i++) {
                float4 v = make_float4(m[i].x * ex, m[i].y * ex, m[i].z * ex, m[i].w * ex);
                atomicAdd((float4*)(aggp + 4 * i), v);
            }
        }
    }
}

// ============ node update MLP via bf16 MMA + ldmatrix (64 nodes/tile) ============
#define N_O_A 0
#define N_O_HID 9216
#define N_O_B1 26624
#define N_O_B2 43008
#define N_O_BIAS 59392
#define NODE_SMEM_B 60416

__global__ void __launch_bounds__(256) k_node_mma(
        const float* __restrict__ W1, const float* __restrict__ b1,
        const float* __restrict__ W2, const float* __restrict__ b2,
        const int* __restrict__ batch, int do_pool) {
    extern __shared__ char smem[];
    uint32_t* sB1u = (uint32_t*)(smem + N_O_B1);
    uint32_t* sB2u = (uint32_t*)(smem + N_O_B2);
    float* sBias = (float*)(smem + N_O_BIAS);
    int tid = threadIdx.x;
    int lane = tid & 31, wid = tid >> 5;
    int g = lane >> 2, tg = lane & 3;

    // pack W1 [64x128] fragments (4 ks x 16 ntg)
    for (int idx = tid; idx < 4 * 16 * 32; idx += 256) {
        int l = idx & 31, nt = (idx >> 5) & 15, ks = idx >> 9;
        int gg = l >> 2, tt = l & 3;
        int n = nt * 8 + gg, k0 = ks * 16 + 2 * tt;
        uint2 v;
        v.x = f2bf2(W1[k0 * NH + n], W1[(k0 + 1) * NH + n]);
        v.y = f2bf2(W1[(k0 + 8) * NH + n], W1[(k0 + 9) * NH + n]);
        *(uint2*)(sB1u + (size_t)((ks * 16 + nt) * 64 + 2 * l)) = v;
    }
    // pack W2 [128x64] fragments (8 ks x 8 ntg)
    for (int idx = tid; idx < 8 * 8 * 32; idx += 256) {
        int l = idx & 31, nt = (idx >> 5) & 7, ks = idx >> 8;
        int gg = l >> 2, tt = l & 3;
        int n = nt * 8 + gg, k0 = ks * 16 + 2 * tt;
        uint2 v;
        v.x = f2bf2(W2[k0 * ND + n], W2[(k0 + 1) * ND + n]);
        v.y = f2bf2(W2[(k0 + 8) * ND + n], W2[(k0 + 9) * ND + n]);
        *(uint2*)(sB2u + (size_t)((ks * 8 + nt) * 64 + 2 * l)) = v;
    }
    if (tid < 128) sBias[tid] = b1[tid];
    if (tid < 64)  sBias[128 + tid] = b2[tid];
    __syncthreads();

    int mt = wid & 3;
    int nh = wid >> 2;
    int lrow = lane & 15;
    int lcol = (lane >> 4) * 16;

    for (int tile = blockIdx.x; tile < NTILES_N; tile += gridDim.x) {
        int base = tile * 64;
        int nrows = NN - base; if (nrows > 64) nrows = 64;
        // ---- load A = agg/denom -> bf16 [64][72] (144 B rows) ----
        {
            int e_l = tid >> 2, q = tid & 3;
            float4 v0 = make_float4(0.f,0.f,0.f,0.f), v1 = v0, v2 = v0, v3 = v0;
            if (e_l < nrows) {
                int n = base + e_l;
                float dn = g_denom[n];
                float invd = dn > 0.f ? 1.f / dn : 0.f;
                const float4* rp = (const float4*)(g_agg + (size_t)n * ND + q * 16);
                v0 = rp[0]; v1 = rp[1]; v2 = rp[2]; v3 = rp[3];
                v0.x *= invd; v0.y *= invd; v0.z *= invd; v0.w *= invd;
                v1.x *= invd; v1.y *= invd; v1.z *= invd; v1.w *= invd;
                v2.x *= invd; v2.y *= invd; v2.z *= invd; v2.w *= invd;
                v3.x *= invd; v3.y *= invd; v3.z *= invd; v3.w *= invd;
            }
            uint4 pA, pB;
            pA.x = f2bf2(v0.x, v0.y); pA.y = f2bf2(v0.z, v0.w);
            pA.z = f2bf2(v1.x, v1.y); pA.w = f2bf2(v1.z, v1.w);
            pB.x = f2bf2(v2.x, v2.y); pB.y = f2bf2(v2.z, v2.w);
            pB.z = f2bf2(v3.x, v3.y); pB.w = f2bf2(v3.z, v3.w);
            *(uint4*)(smem + N_O_A + e_l * 144 + q * 32)      = pA;
            *(uint4*)(smem + N_O_A + e_l * 144 + q * 32 + 16) = pB;
        }
        __syncthreads();

        // ---- GEMM1: hid = A @ W1 (K=64, 4 ks) ----
        float C1[8][4];
        #pragma unroll
        for (int nt = 0; nt < 8; nt++)
            C1[nt][0] = C1[nt][1] = C1[nt][2] = C1[nt][3] = 0.f;
        #pragma unroll
        for (int ks = 0; ks < 4; ks++) {
            uint32_t a0, a1, a2, a3;
            ldmA(a0, a1, a2, a3,
                 smem + N_O_A + (mt * 16 + lrow) * 144 + ks * 32 + lcol);
            #pragma unroll
            for (int nt = 0; nt < 8; nt++) {
                int ntg = nh * 8 + nt;
                uint2 bf = *(const uint2*)(sB1u + (ks * 16 + ntg) * 64 + 2 * lane);
                mma_bf16(C1[nt], a0, a1, a2, a3, bf.x, bf.y);
            }
        }
        #pragma unroll
        for (int nt = 0; nt < 8; nt++) {
            int col = (nh * 8 + nt) * 8 + 2 * tg;
            float bb0 = sBias[col], bb1 = sBias[col + 1];
            uint32_t lo = f2bf2(tanha(C1[nt][0] + bb0), tanha(C1[nt][1] + bb1));
            uint32_t hi = f2bf2(tanha(C1[nt][2] + bb0), tanha(C1[nt][3] + bb1));
            *(uint32_t*)(smem + N_O_HID + (mt * 16 + g) * 272 + col * 2)     = lo;
            *(uint32_t*)(smem + N_O_HID + (mt * 16 + g + 8) * 272 + col * 2) = hi;
        }
        __syncthreads();

        // ---- GEMM2: delta = hid @ W2 (K=128, 8 ks) ----
        float C2[4][4];
        #pragma unroll
        for (int nt = 0; nt < 4; nt++)
            C2[nt][0] = C2[nt][1] = C2[nt][2] = C2[nt][3] = 0.f;
        #pragma unroll
        for (int ks = 0; ks < 8; ks++) {
            uint32_t a0, a1, a2, a3;
            ldmA(a0, a1, a2, a3,
                 smem + N_O_HID + (mt * 16 + lrow) * 272 + ks * 32 + lcol);
            #pragma unroll
            for (int nt = 0; nt < 4; nt++) {
                int ntg = nh * 4 + nt;
                uint2 bf = *(const uint2*)(sB2u + (ks * 8 + ntg) * 64 + 2 * lane);
                mma_bf16(C2[nt], a0, a1, a2, a3, bf.x, bf.y);
            }
        }
        __syncthreads();

        {
            float* dwp = (float*)(smem + N_O_HID);
            #pragma unroll
            for (int nt = 0; nt < 4; nt++) {
                int col = (nh * 4 + nt) * 8 + 2 * tg;
                float bb0 = sBias[128 + col], bb1 = sBias[128 + col + 1];
                *(float2*)(dwp + (mt * 16 + g) * 68 + col)     = make_float2(C2[nt][0] + bb0, C2[nt][1] + bb1);
                *(float2*)(dwp + (mt * 16 + g + 8) * 68 + col) = make_float2(C2[nt][2] + bb0, C2[nt][3] + bb1);
            }
        }
        __syncthreads();

        // ---- epilogue: h += delta, optional fused pooling ----
        {
            int e_l = tid >> 2, cg = tid & 3;
            if (e_l < nrows) {
                int n = base + e_l;
                float* hp = g_h + (size_t)n * ND + cg * 16;
                const float* dw = (const float*)(smem + N_O_HID) + e_l * 68 + cg * 16;
                float4 hv[4];
                #pragma unroll
                for (int i = 0; i < 4; i++) {
                    float4 h = *(float4*)(hp + 4 * i);
                    float4 d = *(const float4*)(dw + 4 * i);
                    hv[i] = make_float4(h.x + d.x, h.y + d.y, h.z + d.z, h.w + d.w);
                    *(float4*)(hp + 4 * i) = hv[i];
                }
                if (do_pool) {
                    int b = batch[n];
                    float* pp = g_pooled + b * ND + cg * 16;
                    #pragma unroll
                    for (int i = 0; i < 4; i++)
                        atomicAdd((float4*)(pp + 4 * i), hv[i]);
                    if (cg == 0) atomicAdd(&g_cnt[b], 1);
                }
            }
        }
    }
}

// ---------------- pooling init + final MLP ----------------
__global__ void k_pool_init() {
    int i = threadIdx.x + blockIdx.x * blockDim.x;
    if (i < NG * ND) g_pooled[i] = 0.f;
    if (i < NG) g_cnt[i] = 0;
}

#define FINAL_SMEM_F (8192 + 4096 + 128 + 32 + 512 + 1024)
__global__ void k_final(const float* __restrict__ W1, const float* __restrict__ b1,
                        const float* __restrict__ W2, const float* __restrict__ b2,
                        float* __restrict__ out) {
    extern __shared__ float sm[];
    float* sW1  = sm;
    float* sW2  = sm + 8192;
    float* sb1  = sm + 12288;
    float* sb2  = sm + 12416;
    float* sP   = sm + 12448;
    float* sHid = sm + 12960;
    int t = threadIdx.x;
    for (int i = t; i < 8192; i += 256) sW1[i] = W1[i];
    for (int i = t; i < 4096; i += 256) sW2[i] = W2[i];
    if (t < 128) sb1[t] = b1[t];
    if (t < 32) sb2[t] = b2[t];
    __syncthreads();

    int w = t >> 5, l = t & 31;
    int g = blockIdx.x * 8 + w;
    if (g >= NG) return;
    float inv = 1.f / (float)max(g_cnt[g], 1);
    float* pw   = sP + w * 64;
    float* hidw = sHid + w * 128;
    float2 pv = *(const float2*)(g_pooled + g * ND + 2 * l);
    pw[2 * l] = pv.x * inv;
    pw[2 * l + 1] = pv.y * inv;
    __syncwarp();
    float4 acc = *(const float4*)(sb1 + 4 * l);
    #pragma unroll 8
    for (int k = 0; k < 64; k++) {
        float a = pw[k];
        float4 wv = *(const float4*)(sW1 + k * 128 + 4 * l);
        acc.x = fmaf(a, wv.x, acc.x);
        acc.y = fmaf(a, wv.y, acc.y);
        acc.z = fmaf(a, wv.z, acc.z);
        acc.w = fmaf(a, wv.w, acc.w);
    }
    acc.x = tanhf(acc.x); acc.y = tanhf(acc.y);
    acc.z = tanhf(acc.z); acc.w = tanhf(acc.w);
    *(float4*)(hidw + 4 * l) = acc;
    __syncwarp();
    float o = sb2[l];
    #pragma unroll 8
    for (int k = 0; k < 128; k += 4) {
        float4 hv = *(const float4*)(hidw + k);
        o = fmaf(hv.x, sW2[(k    ) * 32 + l], o);
        o = fmaf(hv.y, sW2[(k + 1) * 32 + l], o);
        o = fmaf(hv.z, sW2[(k + 2) * 32 + l], o);
        o = fmaf(hv.w, sW2[(k + 3) * 32 + l], o);
    }
    out[g * OD + l] = o;
}

// ---------------- launch ----------------
extern "C" void kernel_launch(void* const* d_in, const int* in_sizes, int n_in,
                              void* d_out, int out_size) {
    const float *x, *ea, *Wd, *fW1, *fb1, *fW2, *fb2, *av;
    const float *oW1, *ob1, *oW2, *ob2, *nW1, *nb1, *nW2, *nb2;
    const int *ei, *batch;

    if (in_sizes[2] == 2 * NE) {
        x   = (const float*)d_in[0];  ea  = (const float*)d_in[1];
        ei  = (const int*)  d_in[2];  batch = (const int*)d_in[3];
        Wd  = (const float*)d_in[4];
        fW1 = (const float*)d_in[5];  fb1 = (const float*)d_in[6];
        fW2 = (const float*)d_in[7];  fb2 = (const float*)d_in[8];
        av  = (const float*)d_in[9];
        oW1 = (const float*)d_in[10]; ob1 = (const float*)d_in[11];
        oW2 = (const float*)d_in[12]; ob2 = (const float*)d_in[13];
        nW1 = (const float*)d_in[14]; nb1 = (const float*)d_in[15];
        nW2 = (const float*)d_in[16]; nb2 = (const float*)d_in[17];
    } else {
        x   = (const float*)d_in[0];  ea  = (const float*)d_in[1];
        Wd  = (const float*)d_in[2];
        fW1 = (const float*)d_in[3];  fb1 = (const float*)d_in[4];
        fW2 = (const float*)d_in[5];  fb2 = (const float*)d_in[6];
        av  = (const float*)d_in[7];
        oW1 = (const float*)d_in[8];  ob1 = (const float*)d_in[9];
        oW2 = (const float*)d_in[10]; ob2 = (const float*)d_in[11];
        nW1 = (const float*)d_in[12]; nb1 = (const float*)d_in[13];
        nW2 = (const float*)d_in[14]; nb2 = (const float*)d_in[15];
        ei  = (const int*)d_in[16];   batch = (const int*)d_in[17];
    }

    cudaFuncSetAttribute(k_edge_mma, cudaFuncAttributeMaxDynamicSharedMemorySize,
                         EDGE_SMEM_B);
    cudaFuncSetAttribute(k_node_mma, cudaFuncAttributeMaxDynamicSharedMemorySize,
                         NODE_SMEM_B);
    cudaFuncSetAttribute(k_final, cudaFuncAttributeMaxDynamicSharedMemorySize,
                         FINAL_SMEM_F * 4);

    k_copy_h<<<(NN * ND + 255) / 256, 256>>>(x);
    k_pool_init<<<(NG * ND + 255) / 256, 256>>>();

    for (int i = 0; i < NL; i++) {
        k_dense<<<1480, 256>>>(Wd + i * ND * ND);
        k_edge_mma<<<592, 256, EDGE_SMEM_B>>>(
            ea, ei,
            fW1 + i * ED * NH, fb1 + i * NH,
            fW2 + i * NH * ND, fb2 + i * ND,
            av + i * ND);
        k_node_mma<<<444, 256, NODE_SMEM_B>>>(
            oW1 + i * ND * NH, ob1 + i * NH,
            oW2 + i * NH * ND, ob2 + i * ND,
            batch, (i == NL - 1) ? 1 : 0);
    }

    k_final<<<16, 256, FINAL_SMEM_F * 4>>>(nW1, nb1, nW2, nb2, (float*)d_out);
}